// round 2
// baseline (speedup 1.0000x reference)
#include <cuda_runtime.h>
#include <math.h>

// Problem constants
#define BB 4
#define TT 2048
#define DD 1024
#define HH 16
#define HD 64
#define MROWS (BB * TT)   // 8192

// Scratch (device globals; no allocation allowed)
__device__ float g_q[BB * HH * TT * HD];   // [b,h,t,hd]
__device__ float g_k[BB * HH * TT * HD];
__device__ float g_v[BB * HH * TT * HD];
__device__ float g_att[MROWS * DD];        // [b*t, d] attention output

// ---------------------------------------------------------------------------
// Tiled fp32 SGEMM: C[M,N] = A[M,K] @ W[K,N] + bias
// BM=BN=128, BK=8, 256 threads, 8x8 microtile, double-buffered smem
// (one __syncthreads per K-step; next tile's global loads issued before
// compute on the current tile).
// MODE 0: QKV gemm -> scatter into g_q/g_k/g_v as [b,h,t,hd]
// MODE 1: proj gemm, A := g_att, C := output
// ---------------------------------------------------------------------------
template <int MODE>
__global__ __launch_bounds__(256) void sgemm128(
    const float* __restrict__ A, const float* __restrict__ W,
    const float* __restrict__ bias, float* __restrict__ C,
    const int N, const int K)
{
    __shared__ float As[2][8][128];   // transposed A tile: As[buf][k][m]
    __shared__ float Bs[2][8][128];   // Bs[buf][k][n]

    const int tid = threadIdx.x;
    const int tx = tid & 15;       // 0..15 (N direction)
    const int ty = tid >> 4;       // 0..15 (M direction)

    const int rowBase = blockIdx.y * 128;
    const int colBase = blockIdx.x * 128;

    const float* Ab = (MODE == 1) ? (const float*)g_att : A;

    // global load mappings
    const int ar = tid >> 1;            // A row within tile (0..127)
    const int ak = (tid & 1) * 4;       // A k offset (0 or 4)
    const int br = tid >> 5;            // B k row (0..7)
    const int bc = (tid & 31) * 4;      // B col offset (0..124)

    const float* aptr = Ab + (rowBase + ar) * K + ak;
    const float* bptr = W + br * N + colBase + bc;

    float acc[8][8];
#pragma unroll
    for (int i = 0; i < 8; ++i)
#pragma unroll
        for (int j = 0; j < 8; ++j) acc[i][j] = 0.f;

    // prologue: fill buffer 0
    {
        const float4 av = *(const float4*)(aptr);
        const float4 bv = *(const float4*)(bptr);
        As[0][ak + 0][ar] = av.x;
        As[0][ak + 1][ar] = av.y;
        As[0][ak + 2][ar] = av.z;
        As[0][ak + 3][ar] = av.w;
        *(float4*)&Bs[0][br][bc] = bv;
    }
    __syncthreads();

    int cur = 0;
    for (int k0 = 8; k0 <= K; k0 += 8) {
        // issue next tile's global loads early (overlap with compute)
        float4 av, bv;
        const bool more = (k0 < K);
        if (more) {
            av = *(const float4*)(aptr + k0);
            bv = *(const float4*)(bptr + k0 * N);
        }

        // compute on current buffer
#pragma unroll
        for (int kk = 0; kk < 8; ++kk) {
            float a[8], b[8];
            *(float4*)&a[0] = *(const float4*)&As[cur][kk][ty * 8];
            *(float4*)&a[4] = *(const float4*)&As[cur][kk][ty * 8 + 4];
            *(float4*)&b[0] = *(const float4*)&Bs[cur][kk][tx * 8];
            *(float4*)&b[4] = *(const float4*)&Bs[cur][kk][tx * 8 + 4];
#pragma unroll
            for (int i = 0; i < 8; ++i)
#pragma unroll
                for (int j = 0; j < 8; ++j)
                    acc[i][j] += a[i] * b[j];
        }

        if (more) {
            const int nxt = cur ^ 1;
            As[nxt][ak + 0][ar] = av.x;
            As[nxt][ak + 1][ar] = av.y;
            As[nxt][ak + 2][ar] = av.z;
            As[nxt][ak + 3][ar] = av.w;
            *(float4*)&Bs[nxt][br][bc] = bv;
            __syncthreads();
            cur = nxt;
        }
    }

    // epilogue
#pragma unroll
    for (int i = 0; i < 8; ++i) {
        const int r = rowBase + ty * 8 + i;
#pragma unroll
        for (int j = 0; j < 8; ++j) {
            const int c = colBase + tx * 8 + j;
            const float val = acc[i][j] + bias[c];
            if (MODE == 0) {
                const int which = c >> 10;       // 0=q 1=k 2=v
                const int dcol  = c & 1023;
                const int hh    = dcol >> 6;
                const int hd    = dcol & 63;
                const int bidx  = r >> 11;       // r / 2048
                const int t     = r & 2047;
                float* dst = (which == 0) ? g_q : (which == 1) ? g_k : g_v;
                dst[(((bidx * HH) + hh) * TT + t) * HD + hd] = val;
            } else {
                C[r * N + c] = val;
            }
        }
    }
}

// ---------------------------------------------------------------------------
// Flash attention (causal), fp32. One block = one (b, h, 64-query tile).
// 256 threads as 16x16; each thread owns a 4x4 microtile of the 64x64 S/P/O
// tiles. Smem: Q transposed [d][q], K transposed [d][k] (buffer reused for
// P row-major [q][k]), V [k][d]. 3 * 64*64 * 4B = 48KB exactly.
// ---------------------------------------------------------------------------
__global__ __launch_bounds__(256) void flash_attn_kernel()
{
    __shared__ float QT[64 * 64];   // QT[d*64 + q], pre-scaled by 1/sqrt(hd)
    __shared__ float KP[64 * 64];   // KT[d*64 + k], then reused as P[q*64 + k]
    __shared__ float Vs[64 * 64];   // Vs[k*64 + d]

    const int tid = threadIdx.x;
    const int tx = tid & 15;        // key/out-col direction
    const int ty = tid >> 4;        // query-row direction
    const int qi = blockIdx.x;      // query tile 0..31
    const int h  = blockIdx.y;
    const int b  = blockIdx.z;

    const int base = ((b * HH) + h) * TT * HD;
    const float* Qg = g_q + base + qi * 64 * HD;
    const float* Kg = g_k + base;
    const float* Vg = g_v + base;

    // --- load Q tile transposed + scaled ---
    {
        const int r  = tid >> 2;          // query row 0..63
        const int c0 = (tid & 3) * 16;    // starting d
        const float* src = Qg + r * 64 + c0;
#pragma unroll
        for (int u = 0; u < 4; ++u) {
            const float4 v = *(const float4*)(src + u * 4);
            const int d = c0 + u * 4;
            QT[(d + 0) * 64 + r] = v.x * 0.125f;
            QT[(d + 1) * 64 + r] = v.y * 0.125f;
            QT[(d + 2) * 64 + r] = v.z * 0.125f;
            QT[(d + 3) * 64 + r] = v.w * 0.125f;
        }
    }

    float m_i[4], l_i[4], acc[4][4];
#pragma unroll
    for (int i = 0; i < 4; ++i) {
        m_i[i] = -INFINITY;
        l_i[i] = 0.f;
#pragma unroll
        for (int j = 0; j < 4; ++j) acc[i][j] = 0.f;
    }

    for (int kt = 0; kt <= qi; ++kt) {
        // --- load K tile transposed, V tile direct ---
        {
            const int r  = tid >> 2;
            const int c0 = (tid & 3) * 16;
            const float* ksrc = Kg + (kt * 64 + r) * 64 + c0;
#pragma unroll
            for (int u = 0; u < 4; ++u) {
                const float4 v = *(const float4*)(ksrc + u * 4);
                const int d = c0 + u * 4;
                KP[(d + 0) * 64 + r] = v.x;
                KP[(d + 1) * 64 + r] = v.y;
                KP[(d + 2) * 64 + r] = v.z;
                KP[(d + 3) * 64 + r] = v.w;
            }
            const float4* vsrc = (const float4*)(Vg + kt * 64 * 64);
#pragma unroll
            for (int u = 0; u < 4; ++u) {
                const int f = tid + u * 256;
                ((float4*)Vs)[f] = vsrc[f];
            }
        }
        __syncthreads();

        // --- S = (Q/8) @ K^T, 4x4 microtile ---
        float s[4][4];
#pragma unroll
        for (int i = 0; i < 4; ++i)
#pragma unroll
            for (int j = 0; j < 4; ++j) s[i][j] = 0.f;

#pragma unroll 8
        for (int d = 0; d < 64; ++d) {
            float a[4], bq[4];
            *(float4*)&a[0]  = *(const float4*)&QT[d * 64 + ty * 4];
            *(float4*)&bq[0] = *(const float4*)&KP[d * 64 + tx * 4];
#pragma unroll
            for (int i = 0; i < 4; ++i)
#pragma unroll
                for (int j = 0; j < 4; ++j)
                    s[i][j] += a[i] * bq[j];
        }

        // --- causal mask (diagonal tile only; local indices comparable) ---
        if (kt == qi) {
#pragma unroll
            for (int i = 0; i < 4; ++i) {
                const int qrow = ty * 4 + i;
#pragma unroll
                for (int j = 0; j < 4; ++j) {
                    if (tx * 4 + j > qrow) s[i][j] = -INFINITY;
                }
            }
        }

        // --- online softmax (row groups = 16 lanes, xor-shuffle width 16) ---
        float alpha[4];
#pragma unroll
        for (int i = 0; i < 4; ++i) {
            float mt = fmaxf(fmaxf(s[i][0], s[i][1]), fmaxf(s[i][2], s[i][3]));
#pragma unroll
            for (int o = 8; o >= 1; o >>= 1)
                mt = fmaxf(mt, __shfl_xor_sync(0xffffffffu, mt, o));
            const float mnew = fmaxf(m_i[i], mt);
            alpha[i] = __expf(m_i[i] - mnew);
            m_i[i] = mnew;
            float ls = 0.f;
#pragma unroll
            for (int j = 0; j < 4; ++j) {
                const float p = __expf(s[i][j] - mnew);
                s[i][j] = p;
                ls += p;
            }
#pragma unroll
            for (int o = 8; o >= 1; o >>= 1)
                ls += __shfl_xor_sync(0xffffffffu, ls, o);
            l_i[i] = l_i[i] * alpha[i] + ls;
        }

        __syncthreads();   // all warps done reading KP as K

        // --- write P into KP buffer, row-major [q][k] ---
#pragma unroll
        for (int i = 0; i < 4; ++i)
#pragma unroll
            for (int j = 0; j < 4; ++j)
                KP[(ty * 4 + i) * 64 + tx * 4 + j] = s[i][j];
        __syncthreads();

        // --- rescale accumulator, then O += P @ V ---
#pragma unroll
        for (int i = 0; i < 4; ++i)
#pragma unroll
            for (int j = 0; j < 4; ++j) acc[i][j] *= alpha[i];

#pragma unroll 8
        for (int kk = 0; kk < 64; ++kk) {
            float bv[4];
            *(float4*)&bv[0] = *(const float4*)&Vs[kk * 64 + tx * 4];
            float a0 = KP[(ty * 4 + 0) * 64 + kk];
            float a1 = KP[(ty * 4 + 1) * 64 + kk];
            float a2 = KP[(ty * 4 + 2) * 64 + kk];
            float a3 = KP[(ty * 4 + 3) * 64 + kk];
#pragma unroll
            for (int j = 0; j < 4; ++j) {
                acc[0][j] += a0 * bv[j];
                acc[1][j] += a1 * bv[j];
                acc[2][j] += a2 * bv[j];
                acc[3][j] += a3 * bv[j];
            }
        }
        __syncthreads();   // before next tile overwrites KP / Vs
    }

    // --- epilogue: normalize and write [b*t, d] for proj gemm ---
#pragma unroll
    for (int i = 0; i < 4; ++i) {
        const float inv = 1.f / l_i[i];
        const int t = qi * 64 + ty * 4 + i;
        float4 o;
        o.x = acc[i][0] * inv;
        o.y = acc[i][1] * inv;
        o.z = acc[i][2] * inv;
        o.w = acc[i][3] * inv;
        *(float4*)&g_att[(b * TT + t) * DD + h * HD + tx * 4] = o;
    }
}

// ---------------------------------------------------------------------------
extern "C" void kernel_launch(void* const* d_in, const int* in_sizes, int n_in,
                              void* d_out, int out_size)
{
    const float* x      = (const float*)d_in[0];
    const float* qkv_w  = (const float*)d_in[1];
    const float* qkv_b  = (const float*)d_in[2];
    const float* proj_w = (const float*)d_in[3];
    const float* proj_b = (const float*)d_in[4];
    float* out = (float*)d_out;

    // 1) QKV projection: [8192,1024]@[1024,3072], scatter into q/k/v [b,h,t,hd]
    sgemm128<0><<<dim3(3 * DD / 128, MROWS / 128), 256>>>(
        x, qkv_w, qkv_b, nullptr, 3 * DD, DD);

    // 2) Causal flash attention per (q-tile, head, batch)
    flash_attn_kernel<<<dim3(TT / 64, HH, BB), 256>>>();

    // 3) Output projection: [8192,1024]@[1024,1024] + bias
    sgemm128<1><<<dim3(DD / 128, MROWS / 128), 256>>>(
        nullptr, proj_w, proj_b, out, DD, DD);
}

// round 3
// speedup vs baseline: 1.1651x; 1.1651x over previous
#include <cuda_runtime.h>
#include <math.h>

// Problem constants
#define BB 4
#define TT 2048
#define DD 1024
#define HH 16
#define HD 64
#define MROWS (BB * TT)   // 8192
#define PADS 136          // smem row stride (floats): 128 + 8 pad -> conflict-free frag loads

// Scratch (device globals; no allocation allowed)
__device__ float g_q[BB * HH * TT * HD];   // [b,h,t,hd]
__device__ float g_k[BB * HH * TT * HD];
__device__ float g_v[BB * HH * TT * HD];
__device__ float g_att[MROWS * DD];        // [b*t, d] attention output

// ---------------------------------------------------------------------------
// tf32 helpers (3xTF32 split: x = hi + lo, both tf32-rounded; error ~2^-22)
// ---------------------------------------------------------------------------
__device__ __forceinline__ unsigned f2tf32(float x) {
    unsigned r;
    asm("cvt.rna.tf32.f32 %0, %1;" : "=r"(r) : "f"(x));
    return r;
}

__device__ __forceinline__ void mma_tf32(float* c, const unsigned* a, const unsigned* b) {
    asm volatile(
        "mma.sync.aligned.m16n8k8.row.col.f32.tf32.tf32.f32 "
        "{%0,%1,%2,%3}, {%4,%5,%6,%7}, {%8,%9}, {%0,%1,%2,%3};"
        : "+f"(c[0]), "+f"(c[1]), "+f"(c[2]), "+f"(c[3])
        : "r"(a[0]), "r"(a[1]), "r"(a[2]), "r"(a[3]), "r"(b[0]), "r"(b[1]));
}

// ---------------------------------------------------------------------------
// tf32 tensor-core GEMM with 3xTF32 compensation:
// C[M,N] = A[M,K] @ W[K,N] + bias, fp32-accurate.
// BM=BN=128, BK=8, 256 threads = 8 warps (2x4 M x N), warp tile 64x32,
// m16n8k8 fragments, double-buffered smem (hi & lo planes).
// MODE 0: QKV gemm -> scatter into g_q/g_k/g_v as [b,h,t,hd]
// MODE 1: proj gemm, A := g_att, C := output
// ---------------------------------------------------------------------------
template <int MODE>
__global__ __launch_bounds__(256) void gemm_tf32(
    const float* __restrict__ A, const float* __restrict__ W,
    const float* __restrict__ bias, float* __restrict__ C,
    const int N, const int K)
{
    __shared__ float As_hi[2][8 * PADS];   // [k][m] transposed
    __shared__ float As_lo[2][8 * PADS];
    __shared__ float Bs_hi[2][8 * PADS];   // [k][n]
    __shared__ float Bs_lo[2][8 * PADS];

    const int tid  = threadIdx.x;
    const int lane = tid & 31;
    const int wid  = tid >> 5;
    const int warp_m = wid >> 2;          // 0..1  -> 64-row slab
    const int warp_n = wid & 3;           // 0..3  -> 32-col slab
    const int g  = lane >> 2;             // 0..7
    const int t4 = lane & 3;              // 0..3

    const int rowBase = blockIdx.y * 128;
    const int colBase = blockIdx.x * 128;

    const float* Ab = (MODE == 1) ? (const float*)g_att : A;

    // global load mappings (one float4 per thread per matrix per BK=8 step)
    const int ar = tid >> 1;              // A row in tile (0..127)
    const int ak = (tid & 1) * 4;         // A k offset (0 or 4)
    const int br = tid >> 5;              // B k row (0..7)
    const int bc = (tid & 31) * 4;        // B col offset (0..124)

    const float* aptr = Ab + (rowBase + ar) * K + ak;
    const float* bptr = W + br * N + colBase + bc;

    float acc[4][4][4];                   // [mf][nf][reg]
#pragma unroll
    for (int mf = 0; mf < 4; ++mf)
#pragma unroll
        for (int nf = 0; nf < 4; ++nf)
#pragma unroll
            for (int r = 0; r < 4; ++r) acc[mf][nf][r] = 0.f;

    // ---- store helper: split float4 into tf32 hi/lo and write smem ----
    auto stageA = [&](int buf, float4 av) {
#pragma unroll
        for (int u = 0; u < 4; ++u) {
            const float x = (&av.x)[u];
            const float hi = __uint_as_float(f2tf32(x));
            const float lo = __uint_as_float(f2tf32(x - hi));
            As_hi[buf][(ak + u) * PADS + ar] = hi;
            As_lo[buf][(ak + u) * PADS + ar] = lo;
        }
    };
    auto stageB = [&](int buf, float4 bv) {
        float4 hv, lv;
#pragma unroll
        for (int u = 0; u < 4; ++u) {
            const float x = (&bv.x)[u];
            const float hi = __uint_as_float(f2tf32(x));
            (&hv.x)[u] = hi;
            (&lv.x)[u] = __uint_as_float(f2tf32(x - hi));
        }
        *(float4*)&Bs_hi[buf][br * PADS + bc] = hv;
        *(float4*)&Bs_lo[buf][br * PADS + bc] = lv;
    };

    // prologue: fill buffer 0
    stageA(0, *(const float4*)aptr);
    stageB(0, *(const float4*)bptr);
    __syncthreads();

    int cur = 0;
    for (int k0 = 8; k0 <= K; k0 += 8) {
        float4 av, bv;
        const bool more = (k0 < K);
        if (more) {
            av = *(const float4*)(aptr + k0);
            bv = *(const float4*)(bptr + k0 * N);
        }

        // ---- load B fragments for this k8 (hi & lo) ----
        unsigned bfh[4][2], bfl[4][2];
#pragma unroll
        for (int nf = 0; nf < 4; ++nf) {
            const int col0 = warp_n * 32 + nf * 8 + g;
            bfh[nf][0] = __float_as_uint(Bs_hi[cur][t4 * PADS + col0]);
            bfh[nf][1] = __float_as_uint(Bs_hi[cur][(t4 + 4) * PADS + col0]);
            bfl[nf][0] = __float_as_uint(Bs_lo[cur][t4 * PADS + col0]);
            bfl[nf][1] = __float_as_uint(Bs_lo[cur][(t4 + 4) * PADS + col0]);
        }

#pragma unroll
        for (int mf = 0; mf < 4; ++mf) {
            const int row0 = warp_m * 64 + mf * 16 + g;
            unsigned afh[4], afl[4];
            afh[0] = __float_as_uint(As_hi[cur][t4 * PADS + row0]);
            afh[1] = __float_as_uint(As_hi[cur][t4 * PADS + row0 + 8]);
            afh[2] = __float_as_uint(As_hi[cur][(t4 + 4) * PADS + row0]);
            afh[3] = __float_as_uint(As_hi[cur][(t4 + 4) * PADS + row0 + 8]);
            afl[0] = __float_as_uint(As_lo[cur][t4 * PADS + row0]);
            afl[1] = __float_as_uint(As_lo[cur][t4 * PADS + row0 + 8]);
            afl[2] = __float_as_uint(As_lo[cur][(t4 + 4) * PADS + row0]);
            afl[3] = __float_as_uint(As_lo[cur][(t4 + 4) * PADS + row0 + 8]);
#pragma unroll
            for (int nf = 0; nf < 4; ++nf) {
                mma_tf32(acc[mf][nf], afh, bfh[nf]);   // hi*hi
                mma_tf32(acc[mf][nf], afh, bfl[nf]);   // hi*lo
                mma_tf32(acc[mf][nf], afl, bfh[nf]);   // lo*hi
            }
        }

        if (more) {
            const int nxt = cur ^ 1;
            stageA(nxt, av);
            stageB(nxt, bv);
            __syncthreads();
            cur = nxt;
        }
    }

    // ---- epilogue: bias + store (fragment layout -> global) ----
#pragma unroll
    for (int mf = 0; mf < 4; ++mf) {
#pragma unroll
        for (int nf = 0; nf < 4; ++nf) {
#pragma unroll
            for (int rr = 0; rr < 4; ++rr) {
                const int r = rowBase + warp_m * 64 + mf * 16 + g + (rr >> 1) * 8;
                const int c = colBase + warp_n * 32 + nf * 8 + t4 * 2 + (rr & 1);
                const float val = acc[mf][nf][rr] + bias[c];
                if (MODE == 0) {
                    const int which = c >> 10;       // 0=q 1=k 2=v
                    const int dcol  = c & 1023;
                    const int hh    = dcol >> 6;
                    const int hd    = dcol & 63;
                    const int bidx  = r >> 11;       // r / 2048
                    const int t     = r & 2047;
                    float* dst = (which == 0) ? g_q : (which == 1) ? g_k : g_v;
                    dst[(((bidx * HH) + hh) * TT + t) * HD + hd] = val;
                } else {
                    C[r * N + c] = val;
                }
            }
        }
    }
}

// ---------------------------------------------------------------------------
// Flash attention (causal), fp32 — UNCHANGED from the passing Round-2 kernel.
// ---------------------------------------------------------------------------
__global__ __launch_bounds__(256) void flash_attn_kernel()
{
    __shared__ float QT[64 * 64];   // QT[d*64 + q], pre-scaled by 1/sqrt(hd)
    __shared__ float KP[64 * 64];   // KT[d*64 + k], then reused as P[q*64 + k]
    __shared__ float Vs[64 * 64];   // Vs[k*64 + d]

    const int tid = threadIdx.x;
    const int tx = tid & 15;        // key/out-col direction
    const int ty = tid >> 4;        // query-row direction
    const int qi = blockIdx.x;      // query tile 0..31
    const int h  = blockIdx.y;
    const int b  = blockIdx.z;

    const int base = ((b * HH) + h) * TT * HD;
    const float* Qg = g_q + base + qi * 64 * HD;
    const float* Kg = g_k + base;
    const float* Vg = g_v + base;

    // --- load Q tile transposed + scaled ---
    {
        const int r  = tid >> 2;          // query row 0..63
        const int c0 = (tid & 3) * 16;    // starting d
        const float* src = Qg + r * 64 + c0;
#pragma unroll
        for (int u = 0; u < 4; ++u) {
            const float4 v = *(const float4*)(src + u * 4);
            const int d = c0 + u * 4;
            QT[(d + 0) * 64 + r] = v.x * 0.125f;
            QT[(d + 1) * 64 + r] = v.y * 0.125f;
            QT[(d + 2) * 64 + r] = v.z * 0.125f;
            QT[(d + 3) * 64 + r] = v.w * 0.125f;
        }
    }

    float m_i[4], l_i[4], acc[4][4];
#pragma unroll
    for (int i = 0; i < 4; ++i) {
        m_i[i] = -INFINITY;
        l_i[i] = 0.f;
#pragma unroll
        for (int j = 0; j < 4; ++j) acc[i][j] = 0.f;
    }

    for (int kt = 0; kt <= qi; ++kt) {
        // --- load K tile transposed, V tile direct ---
        {
            const int r  = tid >> 2;
            const int c0 = (tid & 3) * 16;
            const float* ksrc = Kg + (kt * 64 + r) * 64 + c0;
#pragma unroll
            for (int u = 0; u < 4; ++u) {
                const float4 v = *(const float4*)(ksrc + u * 4);
                const int d = c0 + u * 4;
                KP[(d + 0) * 64 + r] = v.x;
                KP[(d + 1) * 64 + r] = v.y;
                KP[(d + 2) * 64 + r] = v.z;
                KP[(d + 3) * 64 + r] = v.w;
            }
            const float4* vsrc = (const float4*)(Vg + kt * 64 * 64);
#pragma unroll
            for (int u = 0; u < 4; ++u) {
                const int f = tid + u * 256;
                ((float4*)Vs)[f] = vsrc[f];
            }
        }
        __syncthreads();

        // --- S = (Q/8) @ K^T, 4x4 microtile ---
        float s[4][4];
#pragma unroll
        for (int i = 0; i < 4; ++i)
#pragma unroll
            for (int j = 0; j < 4; ++j) s[i][j] = 0.f;

#pragma unroll 8
        for (int d = 0; d < 64; ++d) {
            float a[4], bq[4];
            *(float4*)&a[0]  = *(const float4*)&QT[d * 64 + ty * 4];
            *(float4*)&bq[0] = *(const float4*)&KP[d * 64 + tx * 4];
#pragma unroll
            for (int i = 0; i < 4; ++i)
#pragma unroll
                for (int j = 0; j < 4; ++j)
                    s[i][j] += a[i] * bq[j];
        }

        // --- causal mask (diagonal tile only; local indices comparable) ---
        if (kt == qi) {
#pragma unroll
            for (int i = 0; i < 4; ++i) {
                const int qrow = ty * 4 + i;
#pragma unroll
                for (int j = 0; j < 4; ++j) {
                    if (tx * 4 + j > qrow) s[i][j] = -INFINITY;
                }
            }
        }

        // --- online softmax (row groups = 16 lanes, xor-shuffle width 16) ---
        float alpha[4];
#pragma unroll
        for (int i = 0; i < 4; ++i) {
            float mt = fmaxf(fmaxf(s[i][0], s[i][1]), fmaxf(s[i][2], s[i][3]));
#pragma unroll
            for (int o = 8; o >= 1; o >>= 1)
                mt = fmaxf(mt, __shfl_xor_sync(0xffffffffu, mt, o));
            const float mnew = fmaxf(m_i[i], mt);
            alpha[i] = __expf(m_i[i] - mnew);
            m_i[i] = mnew;
            float ls = 0.f;
#pragma unroll
            for (int j = 0; j < 4; ++j) {
                const float p = __expf(s[i][j] - mnew);
                s[i][j] = p;
                ls += p;
            }
#pragma unroll
            for (int o = 8; o >= 1; o >>= 1)
                ls += __shfl_xor_sync(0xffffffffu, ls, o);
            l_i[i] = l_i[i] * alpha[i] + ls;
        }

        __syncthreads();   // all warps done reading KP as K

        // --- write P into KP buffer, row-major [q][k] ---
#pragma unroll
        for (int i = 0; i < 4; ++i)
#pragma unroll
            for (int j = 0; j < 4; ++j)
                KP[(ty * 4 + i) * 64 + tx * 4 + j] = s[i][j];
        __syncthreads();

        // --- rescale accumulator, then O += P @ V ---
#pragma unroll
        for (int i = 0; i < 4; ++i)
#pragma unroll
            for (int j = 0; j < 4; ++j) acc[i][j] *= alpha[i];

#pragma unroll 8
        for (int kk = 0; kk < 64; ++kk) {
            float bv[4];
            *(float4*)&bv[0] = *(const float4*)&Vs[kk * 64 + tx * 4];
            float a0 = KP[(ty * 4 + 0) * 64 + kk];
            float a1 = KP[(ty * 4 + 1) * 64 + kk];
            float a2 = KP[(ty * 4 + 2) * 64 + kk];
            float a3 = KP[(ty * 4 + 3) * 64 + kk];
#pragma unroll
            for (int j = 0; j < 4; ++j) {
                acc[0][j] += a0 * bv[j];
                acc[1][j] += a1 * bv[j];
                acc[2][j] += a2 * bv[j];
                acc[3][j] += a3 * bv[j];
            }
        }
        __syncthreads();   // before next tile overwrites KP / Vs
    }

    // --- epilogue: normalize and write [b*t, d] for proj gemm ---
#pragma unroll
    for (int i = 0; i < 4; ++i) {
        const float inv = 1.f / l_i[i];
        const int t = qi * 64 + ty * 4 + i;
        float4 o;
        o.x = acc[i][0] * inv;
        o.y = acc[i][1] * inv;
        o.z = acc[i][2] * inv;
        o.w = acc[i][3] * inv;
        *(float4*)&g_att[(b * TT + t) * DD + h * HD + tx * 4] = o;
    }
}

// ---------------------------------------------------------------------------
extern "C" void kernel_launch(void* const* d_in, const int* in_sizes, int n_in,
                              void* d_out, int out_size)
{
    const float* x      = (const float*)d_in[0];
    const float* qkv_w  = (const float*)d_in[1];
    const float* qkv_b  = (const float*)d_in[2];
    const float* proj_w = (const float*)d_in[3];
    const float* proj_b = (const float*)d_in[4];
    float* out = (float*)d_out;

    // 1) QKV projection: [8192,1024]@[1024,3072], scatter into q/k/v [b,h,t,hd]
    gemm_tf32<0><<<dim3(3 * DD / 128, MROWS / 128), 256>>>(
        x, qkv_w, qkv_b, nullptr, 3 * DD, DD);

    // 2) Causal flash attention per (q-tile, head, batch)
    flash_attn_kernel<<<dim3(TT / 64, HH, BB), 256>>>();

    // 3) Output projection: [8192,1024]@[1024,1024] + bias
    gemm_tf32<1><<<dim3(DD / 128, MROWS / 128), 256>>>(
        nullptr, proj_w, proj_b, out, DD, DD);
}

// round 5
// speedup vs baseline: 1.3651x; 1.1716x over previous
#include <cuda_runtime.h>
#include <cuda_bf16.h>
#include <cstdint>
#include <math.h>

// Problem constants
#define BB 4
#define TT 2048
#define DD 1024
#define HH 16
#define HD 64
#define MROWS (BB * TT)   // 8192
#define PADW 9            // smem row stride in uint32 words: 8 kp + 1 pad

// Scratch (device globals; no allocation allowed)
__device__ float g_q[BB * HH * TT * HD];   // [b,h,t,hd]
__device__ float g_k[BB * HH * TT * HD];
__device__ float g_v[BB * HH * TT * HD];
__device__ float g_att[MROWS * DD];        // [b*t, d] attention output

// ---------------------------------------------------------------------------
// bf16x3 helpers (split: x = hi + lo, both bf16; dropped lo*lo term ~2^-16)
// ---------------------------------------------------------------------------
__device__ __forceinline__ uint32_t pack_bf16x2(float e_even, float e_odd) {
    uint32_t r;
    // d.lo = cvt(last operand), d.hi = cvt(first operand)
    asm("cvt.rn.bf16x2.f32 %0, %1, %2;" : "=r"(r) : "f"(e_odd), "f"(e_even));
    return r;
}

__device__ __forceinline__ void mma_bf16(float* c, const uint32_t* a, const uint32_t* b) {
    asm volatile(
        "mma.sync.aligned.m16n8k16.row.col.f32.bf16.bf16.f32 "
        "{%0,%1,%2,%3}, {%4,%5,%6,%7}, {%8,%9}, {%0,%1,%2,%3};"
        : "+f"(c[0]), "+f"(c[1]), "+f"(c[2]), "+f"(c[3])
        : "r"(a[0]), "r"(a[1]), "r"(a[2]), "r"(a[3]), "r"(b[0]), "r"(b[1]));
}

// ---------------------------------------------------------------------------
// bf16x3 tensor-core GEMM: C[M,N] = A[M,K] @ W[K,N] + bias, ~fp32-accurate.
// BM=BN=128, BK=16, 256 threads = 8 warps (2x4), warp tile 64x32,
// m16n8k16 fragments, hi/lo bf16 planes, double-buffered smem.
// Smem layout: [row][kp] with kp = k/2 packed bf16x2 words, k-contiguous.
// MODE 0: QKV gemm -> scatter into g_q/g_k/g_v as [b,h,t,hd]
// MODE 1: proj gemm, A := g_att, C := output
// ---------------------------------------------------------------------------
template <int MODE>
__global__ __launch_bounds__(256) void gemm_bf16x3(
    const float* __restrict__ A, const float* __restrict__ W,
    const float* __restrict__ bias, float* __restrict__ C,
    const int N, const int K)
{
    __shared__ uint32_t As_hi[2][128 * PADW];   // [m][kp]
    __shared__ uint32_t As_lo[2][128 * PADW];
    __shared__ uint32_t Bs_hi[2][128 * PADW];   // [n][kp]
    __shared__ uint32_t Bs_lo[2][128 * PADW];

    const int tid  = threadIdx.x;
    const int lane = tid & 31;
    const int wid  = tid >> 5;
    const int warp_m = wid >> 2;          // 0..1  -> 64-row slab
    const int warp_n = wid & 3;           // 0..3  -> 32-col slab
    const int g  = lane >> 2;             // 0..7
    const int t4 = lane & 3;              // 0..3

    const int rowBase = blockIdx.y * 128;
    const int colBase = blockIdx.x * 128;

    const float* Ab = (MODE == 1) ? (const float*)g_att : A;

    // global load mappings for a 128x16 A tile and 16x128 B tile per step
    const int ar  = tid >> 1;             // A row in tile (0..127)
    const int akb = (tid & 1) * 8;        // A k base (0 or 8), two float4s
    const int bkp = tid >> 5;             // B k-pair (0..7) -> rows 2bkp, 2bkp+1
    const int bc  = (tid & 31) * 4;       // B col offset (0..124)

    const float* aptr  = Ab + (rowBase + ar) * K + akb;
    const float* bptr0 = W + (2 * bkp) * N + colBase + bc;
    const float* bptr1 = W + (2 * bkp + 1) * N + colBase + bc;

    float acc[4][4][4];                   // [mf][nf][reg]
#pragma unroll
    for (int mf = 0; mf < 4; ++mf)
#pragma unroll
        for (int nf = 0; nf < 4; ++nf)
#pragma unroll
            for (int r = 0; r < 4; ++r) acc[mf][nf][r] = 0.f;

    // ---- staging helpers: split fp32 into bf16 hi/lo planes, pack k-pairs ----
    auto stageA = [&](int buf, float4 av0, float4 av1) {
        float e[8];
        *(float4*)&e[0] = av0;
        *(float4*)&e[4] = av1;
#pragma unroll
        for (int p = 0; p < 4; ++p) {
            const float x0 = e[2 * p], x1 = e[2 * p + 1];
            const float h0 = __bfloat162float(__float2bfloat16(x0));
            const float h1 = __bfloat162float(__float2bfloat16(x1));
            As_hi[buf][ar * PADW + akb / 2 + p] = pack_bf16x2(h0, h1);
            As_lo[buf][ar * PADW + akb / 2 + p] = pack_bf16x2(x0 - h0, x1 - h1);
        }
    };
    auto stageB = [&](int buf, float4 bv0, float4 bv1) {
#pragma unroll
        for (int u = 0; u < 4; ++u) {
            const float x0 = (&bv0.x)[u];    // k = 2bkp
            const float x1 = (&bv1.x)[u];    // k = 2bkp+1
            const float h0 = __bfloat162float(__float2bfloat16(x0));
            const float h1 = __bfloat162float(__float2bfloat16(x1));
            Bs_hi[buf][(bc + u) * PADW + bkp] = pack_bf16x2(h0, h1);
            Bs_lo[buf][(bc + u) * PADW + bkp] = pack_bf16x2(x0 - h0, x1 - h1);
        }
    };

    // prologue: fill buffer 0
    stageA(0, *(const float4*)aptr, *(const float4*)(aptr + 4));
    stageB(0, *(const float4*)bptr0, *(const float4*)bptr1);
    __syncthreads();

    int cur = 0;
    for (int k0 = 16; k0 <= K; k0 += 16) {
        float4 av0, av1, bv0, bv1;
        const bool more = (k0 < K);
        if (more) {
            av0 = *(const float4*)(aptr + k0);
            av1 = *(const float4*)(aptr + k0 + 4);
            bv0 = *(const float4*)(bptr0 + k0 * N);
            bv1 = *(const float4*)(bptr1 + k0 * N);
        }

        // ---- B fragments for this k16 (hi & lo): b0 k=2t4.., b1 k=2t4+8.. ----
        uint32_t bfh[4][2], bfl[4][2];
#pragma unroll
        for (int nf = 0; nf < 4; ++nf) {
            const int n0 = warp_n * 32 + nf * 8 + g;
            bfh[nf][0] = Bs_hi[cur][n0 * PADW + t4];
            bfh[nf][1] = Bs_hi[cur][n0 * PADW + t4 + 4];
            bfl[nf][0] = Bs_lo[cur][n0 * PADW + t4];
            bfl[nf][1] = Bs_lo[cur][n0 * PADW + t4 + 4];
        }

#pragma unroll
        for (int mf = 0; mf < 4; ++mf) {
            const int r0 = warp_m * 64 + mf * 16 + g;
            uint32_t afh[4], afl[4];
            afh[0] = As_hi[cur][r0 * PADW + t4];
            afh[1] = As_hi[cur][(r0 + 8) * PADW + t4];
            afh[2] = As_hi[cur][r0 * PADW + t4 + 4];
            afh[3] = As_hi[cur][(r0 + 8) * PADW + t4 + 4];
            afl[0] = As_lo[cur][r0 * PADW + t4];
            afl[1] = As_lo[cur][(r0 + 8) * PADW + t4];
            afl[2] = As_lo[cur][r0 * PADW + t4 + 4];
            afl[3] = As_lo[cur][(r0 + 8) * PADW + t4 + 4];
#pragma unroll
            for (int nf = 0; nf < 4; ++nf) {
                mma_bf16(acc[mf][nf], afh, bfh[nf]);   // hi*hi
                mma_bf16(acc[mf][nf], afh, bfl[nf]);   // hi*lo
                mma_bf16(acc[mf][nf], afl, bfh[nf]);   // lo*hi
            }
        }

        if (more) {
            const int nxt = cur ^ 1;
            stageA(nxt, av0, av1);
            stageB(nxt, bv0, bv1);
            __syncthreads();
            cur = nxt;
        }
    }

    // ---- epilogue: bias + store (m16n8 accumulator layout -> global) ----
#pragma unroll
    for (int mf = 0; mf < 4; ++mf) {
#pragma unroll
        for (int nf = 0; nf < 4; ++nf) {
#pragma unroll
            for (int rr = 0; rr < 4; ++rr) {
                const int r = rowBase + warp_m * 64 + mf * 16 + g + (rr >> 1) * 8;
                const int c = colBase + warp_n * 32 + nf * 8 + t4 * 2 + (rr & 1);
                const float val = acc[mf][nf][rr] + bias[c];
                if (MODE == 0) {
                    const int which = c >> 10;       // 0=q 1=k 2=v
                    const int dcol  = c & 1023;
                    const int hh    = dcol >> 6;
                    const int hd    = dcol & 63;
                    const int bidx  = r >> 11;       // r / 2048
                    const int t     = r & 2047;
                    float* dst = (which == 0) ? g_q : (which == 1) ? g_k : g_v;
                    dst[(((bidx * HH) + hh) * TT + t) * HD + hd] = val;
                } else {
                    C[r * N + c] = val;
                }
            }
        }
    }
}

// ---------------------------------------------------------------------------
// Flash attention (causal), fp32 — UNCHANGED from the passing kernel.
// ---------------------------------------------------------------------------
__global__ __launch_bounds__(256) void flash_attn_kernel()
{
    __shared__ float QT[64 * 64];   // QT[d*64 + q], pre-scaled by 1/sqrt(hd)
    __shared__ float KP[64 * 64];   // KT[d*64 + k], then reused as P[q*64 + k]
    __shared__ float Vs[64 * 64];   // Vs[k*64 + d]

    const int tid = threadIdx.x;
    const int tx = tid & 15;        // key/out-col direction
    const int ty = tid >> 4;        // query-row direction
    const int qi = blockIdx.x;      // query tile 0..31
    const int h  = blockIdx.y;
    const int b  = blockIdx.z;

    const int base = ((b * HH) + h) * TT * HD;
    const float* Qg = g_q + base + qi * 64 * HD;
    const float* Kg = g_k + base;
    const float* Vg = g_v + base;

    // --- load Q tile transposed + scaled ---
    {
        const int r  = tid >> 2;          // query row 0..63
        const int c0 = (tid & 3) * 16;    // starting d
        const float* src = Qg + r * 64 + c0;
#pragma unroll
        for (int u = 0; u < 4; ++u) {
            const float4 v = *(const float4*)(src + u * 4);
            const int d = c0 + u * 4;
            QT[(d + 0) * 64 + r] = v.x * 0.125f;
            QT[(d + 1) * 64 + r] = v.y * 0.125f;
            QT[(d + 2) * 64 + r] = v.z * 0.125f;
            QT[(d + 3) * 64 + r] = v.w * 0.125f;
        }
    }

    float m_i[4], l_i[4], acc[4][4];
#pragma unroll
    for (int i = 0; i < 4; ++i) {
        m_i[i] = -INFINITY;
        l_i[i] = 0.f;
#pragma unroll
        for (int j = 0; j < 4; ++j) acc[i][j] = 0.f;
    }

    for (int kt = 0; kt <= qi; ++kt) {
        // --- load K tile transposed, V tile direct ---
        {
            const int r  = tid >> 2;
            const int c0 = (tid & 3) * 16;
            const float* ksrc = Kg + (kt * 64 + r) * 64 + c0;
#pragma unroll
            for (int u = 0; u < 4; ++u) {
                const float4 v = *(const float4*)(ksrc + u * 4);
                const int d = c0 + u * 4;
                KP[(d + 0) * 64 + r] = v.x;
                KP[(d + 1) * 64 + r] = v.y;
                KP[(d + 2) * 64 + r] = v.z;
                KP[(d + 3) * 64 + r] = v.w;
            }
            const float4* vsrc = (const float4*)(Vg + kt * 64 * 64);
#pragma unroll
            for (int u = 0; u < 4; ++u) {
                const int f = tid + u * 256;
                ((float4*)Vs)[f] = vsrc[f];
            }
        }
        __syncthreads();

        // --- S = (Q/8) @ K^T, 4x4 microtile ---
        float s[4][4];
#pragma unroll
        for (int i = 0; i < 4; ++i)
#pragma unroll
            for (int j = 0; j < 4; ++j) s[i][j] = 0.f;

#pragma unroll 8
        for (int d = 0; d < 64; ++d) {
            float a[4], bq[4];
            *(float4*)&a[0]  = *(const float4*)&QT[d * 64 + ty * 4];
            *(float4*)&bq[0] = *(const float4*)&KP[d * 64 + tx * 4];
#pragma unroll
            for (int i = 0; i < 4; ++i)
#pragma unroll
                for (int j = 0; j < 4; ++j)
                    s[i][j] += a[i] * bq[j];
        }

        // --- causal mask (diagonal tile only; local indices comparable) ---
        if (kt == qi) {
#pragma unroll
            for (int i = 0; i < 4; ++i) {
                const int qrow = ty * 4 + i;
#pragma unroll
                for (int j = 0; j < 4; ++j) {
                    if (tx * 4 + j > qrow) s[i][j] = -INFINITY;
                }
            }
        }

        // --- online softmax (row groups = 16 lanes, xor-shuffle width 16) ---
        float alpha[4];
#pragma unroll
        for (int i = 0; i < 4; ++i) {
            float mt = fmaxf(fmaxf(s[i][0], s[i][1]), fmaxf(s[i][2], s[i][3]));
#pragma unroll
            for (int o = 8; o >= 1; o >>= 1)
                mt = fmaxf(mt, __shfl_xor_sync(0xffffffffu, mt, o));
            const float mnew = fmaxf(m_i[i], mt);
            alpha[i] = __expf(m_i[i] - mnew);
            m_i[i] = mnew;
            float ls = 0.f;
#pragma unroll
            for (int j = 0; j < 4; ++j) {
                const float p = __expf(s[i][j] - mnew);
                s[i][j] = p;
                ls += p;
            }
#pragma unroll
            for (int o = 8; o >= 1; o >>= 1)
                ls += __shfl_xor_sync(0xffffffffu, ls, o);
            l_i[i] = l_i[i] * alpha[i] + ls;
        }

        __syncthreads();   // all warps done reading KP as K

        // --- write P into KP buffer, row-major [q][k] ---
#pragma unroll
        for (int i = 0; i < 4; ++i)
#pragma unroll
            for (int j = 0; j < 4; ++j)
                KP[(ty * 4 + i) * 64 + tx * 4 + j] = s[i][j];
        __syncthreads();

        // --- rescale accumulator, then O += P @ V ---
#pragma unroll
        for (int i = 0; i < 4; ++i)
#pragma unroll
            for (int j = 0; j < 4; ++j) acc[i][j] *= alpha[i];

#pragma unroll 8
        for (int kk = 0; kk < 64; ++kk) {
            float bv[4];
            *(float4*)&bv[0] = *(const float4*)&Vs[kk * 64 + tx * 4];
            float a0 = KP[(ty * 4 + 0) * 64 + kk];
            float a1 = KP[(ty * 4 + 1) * 64 + kk];
            float a2 = KP[(ty * 4 + 2) * 64 + kk];
            float a3 = KP[(ty * 4 + 3) * 64 + kk];
#pragma unroll
            for (int j = 0; j < 4; ++j) {
                acc[0][j] += a0 * bv[j];
                acc[1][j] += a1 * bv[j];
                acc[2][j] += a2 * bv[j];
                acc[3][j] += a3 * bv[j];
            }
        }
        __syncthreads();   // before next tile overwrites KP / Vs
    }

    // --- epilogue: normalize and write [b*t, d] for proj gemm ---
#pragma unroll
    for (int i = 0; i < 4; ++i) {
        const float inv = 1.f / l_i[i];
        const int t = qi * 64 + ty * 4 + i;
        float4 o;
        o.x = acc[i][0] * inv;
        o.y = acc[i][1] * inv;
        o.z = acc[i][2] * inv;
        o.w = acc[i][3] * inv;
        *(float4*)&g_att[(b * TT + t) * DD + h * HD + tx * 4] = o;
    }
}

// ---------------------------------------------------------------------------
extern "C" void kernel_launch(void* const* d_in, const int* in_sizes, int n_in,
                              void* d_out, int out_size)
{
    const float* x      = (const float*)d_in[0];
    const float* qkv_w  = (const float*)d_in[1];
    const float* qkv_b  = (const float*)d_in[2];
    const float* proj_w = (const float*)d_in[3];
    const float* proj_b = (const float*)d_in[4];
    float* out = (float*)d_out;

    // 1) QKV projection: [8192,1024]@[1024,3072], scatter into q/k/v [b,h,t,hd]
    gemm_bf16x3<0><<<dim3(3 * DD / 128, MROWS / 128), 256>>>(
        x, qkv_w, qkv_b, nullptr, 3 * DD, DD);

    // 2) Causal flash attention per (q-tile, head, batch)
    flash_attn_kernel<<<dim3(TT / 64, HH, BB), 256>>>();

    // 3) Output projection: [8192,1024]@[1024,1024] + bias
    gemm_bf16x3<1><<<dim3(DD / 128, MROWS / 128), 256>>>(
        nullptr, proj_w, proj_b, out, DD, DD);
}

// round 6
// speedup vs baseline: 2.1184x; 1.5519x over previous
#include <cuda_runtime.h>
#include <cuda_bf16.h>
#include <cstdint>
#include <math.h>

// Problem constants
#define BB 4
#define TT 2048
#define DD 1024
#define HH 16
#define HD 64
#define MROWS (BB * TT)   // 8192
#define PADW 9            // gemm smem row stride in uint32 words: 8 kp + 1 pad
#define NELEM (BB * HH * TT * HD)

// Scratch (device globals; no allocation allowed)
__device__ __nv_bfloat16 g_q_hi[NELEM], g_q_lo[NELEM];   // [b,h,t,hd], pre-scaled 1/8
__device__ __nv_bfloat16 g_k_hi[NELEM], g_k_lo[NELEM];   // [b,h,t,hd]
__device__ __nv_bfloat16 g_v_hi[NELEM], g_v_lo[NELEM];   // [b,h,hd,t]  (transposed)
__device__ float g_att[MROWS * DD];                      // [b*t, d] attention output

// ---------------------------------------------------------------------------
// bf16x3 helpers (split: x = hi + lo, both bf16; dropped lo*lo term ~2^-16)
// ---------------------------------------------------------------------------
__device__ __forceinline__ uint32_t pack_bf16x2(float e_even, float e_odd) {
    uint32_t r;
    // d.lo = cvt(last operand), d.hi = cvt(first operand)
    asm("cvt.rn.bf16x2.f32 %0, %1, %2;" : "=r"(r) : "f"(e_odd), "f"(e_even));
    return r;
}

__device__ __forceinline__ void mma_bf16(float* c, const uint32_t* a, const uint32_t* b) {
    asm volatile(
        "mma.sync.aligned.m16n8k16.row.col.f32.bf16.bf16.f32 "
        "{%0,%1,%2,%3}, {%4,%5,%6,%7}, {%8,%9}, {%0,%1,%2,%3};"
        : "+f"(c[0]), "+f"(c[1]), "+f"(c[2]), "+f"(c[3])
        : "r"(a[0]), "r"(a[1]), "r"(a[2]), "r"(a[3]), "r"(b[0]), "r"(b[1]));
}

__device__ __forceinline__ void split2(float x0, float x1, uint32_t& hi, uint32_t& lo) {
    const float h0 = __bfloat162float(__float2bfloat16(x0));
    const float h1 = __bfloat162float(__float2bfloat16(x1));
    hi = pack_bf16x2(h0, h1);
    lo = pack_bf16x2(x0 - h0, x1 - h1);
}

// ---------------------------------------------------------------------------
// bf16x3 tensor-core GEMM (mainloop identical to the passing Round-5 kernel).
// MODE 0: QKV gemm -> split-bf16 scatter into q/k (t-major) and v (hd-major)
// MODE 1: proj gemm, A := g_att, C := output
// ---------------------------------------------------------------------------
template <int MODE>
__global__ __launch_bounds__(256) void gemm_bf16x3(
    const float* __restrict__ A, const float* __restrict__ W,
    const float* __restrict__ bias, float* __restrict__ C,
    const int N, const int K)
{
    __shared__ uint32_t As_hi[2][128 * PADW];   // [m][kp]
    __shared__ uint32_t As_lo[2][128 * PADW];
    __shared__ uint32_t Bs_hi[2][128 * PADW];   // [n][kp]
    __shared__ uint32_t Bs_lo[2][128 * PADW];

    const int tid  = threadIdx.x;
    const int lane = tid & 31;
    const int wid  = tid >> 5;
    const int warp_m = wid >> 2;
    const int warp_n = wid & 3;
    const int g  = lane >> 2;
    const int t4 = lane & 3;

    const int rowBase = blockIdx.y * 128;
    const int colBase = blockIdx.x * 128;

    const float* Ab = (MODE == 1) ? (const float*)g_att : A;

    const int ar  = tid >> 1;
    const int akb = (tid & 1) * 8;
    const int bkp = tid >> 5;
    const int bc  = (tid & 31) * 4;

    const float* aptr  = Ab + (rowBase + ar) * K + akb;
    const float* bptr0 = W + (2 * bkp) * N + colBase + bc;
    const float* bptr1 = W + (2 * bkp + 1) * N + colBase + bc;

    float acc[4][4][4];
#pragma unroll
    for (int mf = 0; mf < 4; ++mf)
#pragma unroll
        for (int nf = 0; nf < 4; ++nf)
#pragma unroll
            for (int r = 0; r < 4; ++r) acc[mf][nf][r] = 0.f;

    auto stageA = [&](int buf, float4 av0, float4 av1) {
        float e[8];
        *(float4*)&e[0] = av0;
        *(float4*)&e[4] = av1;
#pragma unroll
        for (int p = 0; p < 4; ++p) {
            const float x0 = e[2 * p], x1 = e[2 * p + 1];
            const float h0 = __bfloat162float(__float2bfloat16(x0));
            const float h1 = __bfloat162float(__float2bfloat16(x1));
            As_hi[buf][ar * PADW + akb / 2 + p] = pack_bf16x2(h0, h1);
            As_lo[buf][ar * PADW + akb / 2 + p] = pack_bf16x2(x0 - h0, x1 - h1);
        }
    };
    auto stageB = [&](int buf, float4 bv0, float4 bv1) {
#pragma unroll
        for (int u = 0; u < 4; ++u) {
            const float x0 = (&bv0.x)[u];
            const float x1 = (&bv1.x)[u];
            const float h0 = __bfloat162float(__float2bfloat16(x0));
            const float h1 = __bfloat162float(__float2bfloat16(x1));
            Bs_hi[buf][(bc + u) * PADW + bkp] = pack_bf16x2(h0, h1);
            Bs_lo[buf][(bc + u) * PADW + bkp] = pack_bf16x2(x0 - h0, x1 - h1);
        }
    };

    stageA(0, *(const float4*)aptr, *(const float4*)(aptr + 4));
    stageB(0, *(const float4*)bptr0, *(const float4*)bptr1);
    __syncthreads();

    int cur = 0;
    for (int k0 = 16; k0 <= K; k0 += 16) {
        float4 av0, av1, bv0, bv1;
        const bool more = (k0 < K);
        if (more) {
            av0 = *(const float4*)(aptr + k0);
            av1 = *(const float4*)(aptr + k0 + 4);
            bv0 = *(const float4*)(bptr0 + k0 * N);
            bv1 = *(const float4*)(bptr1 + k0 * N);
        }

        uint32_t bfh[4][2], bfl[4][2];
#pragma unroll
        for (int nf = 0; nf < 4; ++nf) {
            const int n0 = warp_n * 32 + nf * 8 + g;
            bfh[nf][0] = Bs_hi[cur][n0 * PADW + t4];
            bfh[nf][1] = Bs_hi[cur][n0 * PADW + t4 + 4];
            bfl[nf][0] = Bs_lo[cur][n0 * PADW + t4];
            bfl[nf][1] = Bs_lo[cur][n0 * PADW + t4 + 4];
        }

#pragma unroll
        for (int mf = 0; mf < 4; ++mf) {
            const int r0 = warp_m * 64 + mf * 16 + g;
            uint32_t afh[4], afl[4];
            afh[0] = As_hi[cur][r0 * PADW + t4];
            afh[1] = As_hi[cur][(r0 + 8) * PADW + t4];
            afh[2] = As_hi[cur][r0 * PADW + t4 + 4];
            afh[3] = As_hi[cur][(r0 + 8) * PADW + t4 + 4];
            afl[0] = As_lo[cur][r0 * PADW + t4];
            afl[1] = As_lo[cur][(r0 + 8) * PADW + t4];
            afl[2] = As_lo[cur][r0 * PADW + t4 + 4];
            afl[3] = As_lo[cur][(r0 + 8) * PADW + t4 + 4];
#pragma unroll
            for (int nf = 0; nf < 4; ++nf) {
                mma_bf16(acc[mf][nf], afh, bfh[nf]);
                mma_bf16(acc[mf][nf], afh, bfl[nf]);
                mma_bf16(acc[mf][nf], afl, bfh[nf]);
            }
        }

        if (more) {
            const int nxt = cur ^ 1;
            stageA(nxt, av0, av1);
            stageB(nxt, bv0, bv1);
            __syncthreads();
            cur = nxt;
        }
    }

    // ---- epilogue ----
#pragma unroll
    for (int mf = 0; mf < 4; ++mf) {
#pragma unroll
        for (int nf = 0; nf < 4; ++nf) {
#pragma unroll
            for (int rr = 0; rr < 4; ++rr) {
                const int r = rowBase + warp_m * 64 + mf * 16 + g + (rr >> 1) * 8;
                const int c = colBase + warp_n * 32 + nf * 8 + t4 * 2 + (rr & 1);
                const float val = acc[mf][nf][rr] + bias[c];
                if (MODE == 0) {
                    const int which = c >> 10;       // 0=q 1=k 2=v
                    const int dcol  = c & 1023;
                    const int hh    = dcol >> 6;
                    const int hd    = dcol & 63;
                    const int bidx  = r >> 11;
                    const int t     = r & 2047;
                    if (which == 0) {
                        const float q = val * 0.125f;
                        const __nv_bfloat16 hi = __float2bfloat16(q);
                        const int idx = (((bidx * HH) + hh) * TT + t) * HD + hd;
                        g_q_hi[idx] = hi;
                        g_q_lo[idx] = __float2bfloat16(q - __bfloat162float(hi));
                    } else if (which == 1) {
                        const __nv_bfloat16 hi = __float2bfloat16(val);
                        const int idx = (((bidx * HH) + hh) * TT + t) * HD + hd;
                        g_k_hi[idx] = hi;
                        g_k_lo[idx] = __float2bfloat16(val - __bfloat162float(hi));
                    } else {
                        const __nv_bfloat16 hi = __float2bfloat16(val);
                        const int idx = (((bidx * HH) + hh) * HD + hd) * TT + t;
                        g_v_hi[idx] = hi;
                        g_v_lo[idx] = __float2bfloat16(val - __bfloat162float(hi));
                    }
                } else {
                    C[r * N + c] = val;
                }
            }
        }
    }
}

// ---------------------------------------------------------------------------
// Flash attention (causal) on bf16x3 tensor cores.
// Block = 128 queries x (b,h); 8 warps, each owning 16 query rows (m16).
// KV tiles of 64 keys staged in smem (hi/lo planes, stride 72 bf16 ->
// conflict-free uint32 fragment loads). Q fragments register-resident.
// P fragments built register-direct from S accumulators (A-frag layout
// == accumulator layout for m16n8k16).
// ---------------------------------------------------------------------------
__global__ __launch_bounds__(256, 2) void flash_attn_mma()
{
    __shared__ __align__(16) __nv_bfloat16 Kh[64 * 72], Kl[64 * 72];
    __shared__ __align__(16) __nv_bfloat16 Vh[64 * 72], Vl[64 * 72];

    const int tid  = threadIdx.x;
    const int lane = tid & 31;
    const int wid  = tid >> 5;
    const int g    = lane >> 2;
    const int t4   = lane & 3;
    const int qb   = (TT / 128 - 1) - blockIdx.x;   // largest tiles first
    const int h    = blockIdx.y;
    const int b    = blockIdx.z;

    const int qkbase = ((b * HH) + h) * TT * HD;   // [t][hd] planes
    const int vbase  = ((b * HH) + h) * HD * TT;   // [hd][t] planes

    const int r0 = qb * 128 + wid * 16 + g;        // query rows owned
    const int r1 = r0 + 8;

    // ---- Q fragments, resident for the whole kernel ----
    uint32_t qh[4][4], ql[4][4];
    {
        const uint32_t* Qh32 = (const uint32_t*)(g_q_hi + qkbase);
        const uint32_t* Ql32 = (const uint32_t*)(g_q_lo + qkbase);
#pragma unroll
        for (int kc = 0; kc < 4; ++kc) {
            const int w0 = kc * 8 + t4;
            qh[kc][0] = Qh32[r0 * 32 + w0];
            qh[kc][1] = Qh32[r1 * 32 + w0];
            qh[kc][2] = Qh32[r0 * 32 + w0 + 4];
            qh[kc][3] = Qh32[r1 * 32 + w0 + 4];
            ql[kc][0] = Ql32[r0 * 32 + w0];
            ql[kc][1] = Ql32[r1 * 32 + w0];
            ql[kc][2] = Ql32[r0 * 32 + w0 + 4];
            ql[kc][3] = Ql32[r1 * 32 + w0 + 4];
        }
    }

    float m0 = -INFINITY, m1 = -INFINITY, l0 = 0.f, l1 = 0.f;
    float o[8][4];
#pragma unroll
    for (int nf = 0; nf < 8; ++nf)
#pragma unroll
        for (int r = 0; r < 4; ++r) o[nf][r] = 0.f;

    const uint32_t* Kh32 = (const uint32_t*)Kh;
    const uint32_t* Kl32 = (const uint32_t*)Kl;
    const uint32_t* Vh32 = (const uint32_t*)Vh;
    const uint32_t* Vl32 = (const uint32_t*)Vl;

    const int ntiles = 2 * qb + 2;
    for (int kt = 0; kt < ntiles; ++kt) {
        __syncthreads();   // previous tile's fragment reads done
        // ---- stage K/V tiles (hi & lo) ----
        for (int i = tid; i < 512; i += 256) {
            const int rr = i >> 3, cc = i & 7;
            ((uint4*)(Kh + rr * 72))[cc] =
                ((const uint4*)(g_k_hi + qkbase + (kt * 64 + rr) * 64))[cc];
            ((uint4*)(Kl + rr * 72))[cc] =
                ((const uint4*)(g_k_lo + qkbase + (kt * 64 + rr) * 64))[cc];
            ((uint4*)(Vh + rr * 72))[cc] =
                *(const uint4*)(g_v_hi + vbase + rr * TT + kt * 64 + cc * 8);
            ((uint4*)(Vl + rr * 72))[cc] =
                *(const uint4*)(g_v_lo + vbase + rr * TT + kt * 64 + cc * 8);
        }
        __syncthreads();

        // ---- S = Q @ K^T (bf16x3) ----
        float s[8][4];
#pragma unroll
        for (int nf = 0; nf < 8; ++nf)
#pragma unroll
            for (int r = 0; r < 4; ++r) s[nf][r] = 0.f;

#pragma unroll
        for (int nf = 0; nf < 8; ++nf) {
            const int krow = (nf * 8 + g) * 36;
#pragma unroll
            for (int kc = 0; kc < 4; ++kc) {
                uint32_t bh[2] = { Kh32[krow + kc * 8 + t4], Kh32[krow + kc * 8 + t4 + 4] };
                uint32_t bl[2] = { Kl32[krow + kc * 8 + t4], Kl32[krow + kc * 8 + t4 + 4] };
                mma_bf16(s[nf], qh[kc], bh);
                mma_bf16(s[nf], qh[kc], bl);
                mma_bf16(s[nf], ql[kc], bh);
            }
        }

        // ---- causal mask (only diagonal-region tiles) ----
        if (kt >= 2 * qb) {
            const int kb = kt * 64 + 2 * t4;
#pragma unroll
            for (int nf = 0; nf < 8; ++nf) {
                const int c0 = kb + nf * 8;
                if (c0     > r0) s[nf][0] = -INFINITY;
                if (c0 + 1 > r0) s[nf][1] = -INFINITY;
                if (c0     > r1) s[nf][2] = -INFINITY;
                if (c0 + 1 > r1) s[nf][3] = -INFINITY;
            }
        }

        // ---- online softmax (row reduce over 16 cols: intra-thread + quad shfl) ----
        float mt0 = s[0][0], mt1 = s[0][2];
#pragma unroll
        for (int nf = 0; nf < 8; ++nf) {
            mt0 = fmaxf(mt0, fmaxf(s[nf][0], s[nf][1]));
            mt1 = fmaxf(mt1, fmaxf(s[nf][2], s[nf][3]));
        }
        mt0 = fmaxf(mt0, __shfl_xor_sync(0xffffffffu, mt0, 1));
        mt0 = fmaxf(mt0, __shfl_xor_sync(0xffffffffu, mt0, 2));
        mt1 = fmaxf(mt1, __shfl_xor_sync(0xffffffffu, mt1, 1));
        mt1 = fmaxf(mt1, __shfl_xor_sync(0xffffffffu, mt1, 2));

        const float mn0 = fmaxf(m0, mt0), mn1 = fmaxf(m1, mt1);
        const float a0 = __expf(m0 - mn0), a1 = __expf(m1 - mn1);
        m0 = mn0; m1 = mn1;

        float ls0 = 0.f, ls1 = 0.f;
#pragma unroll
        for (int nf = 0; nf < 8; ++nf) {
            s[nf][0] = __expf(s[nf][0] - mn0); ls0 += s[nf][0];
            s[nf][1] = __expf(s[nf][1] - mn0); ls0 += s[nf][1];
            s[nf][2] = __expf(s[nf][2] - mn1); ls1 += s[nf][2];
            s[nf][3] = __expf(s[nf][3] - mn1); ls1 += s[nf][3];
        }
        ls0 += __shfl_xor_sync(0xffffffffu, ls0, 1);
        ls0 += __shfl_xor_sync(0xffffffffu, ls0, 2);
        ls1 += __shfl_xor_sync(0xffffffffu, ls1, 1);
        ls1 += __shfl_xor_sync(0xffffffffu, ls1, 2);
        l0 = l0 * a0 + ls0;
        l1 = l1 * a1 + ls1;

#pragma unroll
        for (int nf = 0; nf < 8; ++nf) {
            o[nf][0] *= a0; o[nf][1] *= a0;
            o[nf][2] *= a1; o[nf][3] *= a1;
        }

        // ---- O += P @ V (P fragments register-direct from S accumulators) ----
#pragma unroll
        for (int kc = 0; kc < 4; ++kc) {
            uint32_t ph[4], pl[4];
            split2(s[2 * kc][0],     s[2 * kc][1],     ph[0], pl[0]);
            split2(s[2 * kc][2],     s[2 * kc][3],     ph[1], pl[1]);
            split2(s[2 * kc + 1][0], s[2 * kc + 1][1], ph[2], pl[2]);
            split2(s[2 * kc + 1][2], s[2 * kc + 1][3], ph[3], pl[3]);
#pragma unroll
            for (int nf = 0; nf < 8; ++nf) {
                const int vrow = (nf * 8 + g) * 36;
                uint32_t bh[2] = { Vh32[vrow + kc * 8 + t4], Vh32[vrow + kc * 8 + t4 + 4] };
                uint32_t bl[2] = { Vl32[vrow + kc * 8 + t4], Vl32[vrow + kc * 8 + t4 + 4] };
                mma_bf16(o[nf], ph, bh);
                mma_bf16(o[nf], ph, bl);
                mma_bf16(o[nf], pl, bh);
            }
        }
    }

    // ---- epilogue: normalize, write [b*t, d] fp32 for proj gemm ----
    const float i0 = 1.f / l0, i1 = 1.f / l1;
    float* dst0 = g_att + (b * TT + r0) * DD + h * HD;
    float* dst1 = g_att + (b * TT + r1) * DD + h * HD;
#pragma unroll
    for (int nf = 0; nf < 8; ++nf) {
        const int c = nf * 8 + 2 * t4;
        *(float2*)(dst0 + c) = make_float2(o[nf][0] * i0, o[nf][1] * i0);
        *(float2*)(dst1 + c) = make_float2(o[nf][2] * i1, o[nf][3] * i1);
    }
}

// ---------------------------------------------------------------------------
extern "C" void kernel_launch(void* const* d_in, const int* in_sizes, int n_in,
                              void* d_out, int out_size)
{
    const float* x      = (const float*)d_in[0];
    const float* qkv_w  = (const float*)d_in[1];
    const float* qkv_b  = (const float*)d_in[2];
    const float* proj_w = (const float*)d_in[3];
    const float* proj_b = (const float*)d_in[4];
    float* out = (float*)d_out;

    // 1) QKV projection -> split bf16 q/k/v scratch
    gemm_bf16x3<0><<<dim3(3 * DD / 128, MROWS / 128), 256>>>(
        x, qkv_w, qkv_b, nullptr, 3 * DD, DD);

    // 2) Causal flash attention (tensor-core), 128-query blocks
    flash_attn_mma<<<dim3(TT / 128, HH, BB), 256>>>();

    // 3) Output projection
    gemm_bf16x3<1><<<dim3(DD / 128, MROWS / 128), 256>>>(
        nullptr, proj_w, proj_b, out, DD, DD);
}